// round 3
// baseline (speedup 1.0000x reference)
#include <cuda_runtime.h>

// LengthRegulator: ys[b, f, :] = xs[b, i, :] where cum[b,i-1] <= f < cum[b,i],
// else 0.  cum = inclusive cumsum of ds along axis 1.
//
// Two-kernel structure:
//   A: per batch, build frame->row map (int, -1 = zero) in __device__ scratch.
//   B: gather rows via the map (pure bandwidth).

#define BATCH   8
#define TIN     512
#define TOUT    4096
#define DIM     384
#define DIM4    (DIM / 4)          // 96 float4 per row
#define FPB     16                 // frames per block in gather
#define THREADS 512
#define ITERS   ((FPB * DIM4) / THREADS)  // 3

__device__ int g_map[BATCH * TOUT];

__global__ __launch_bounds__(THREADS)
void lr_build_map(const int* __restrict__ ds)
{
    __shared__ int s_cum[TIN];      // inclusive cumsum
    __shared__ int s_d[TIN];

    const int b   = blockIdx.x;
    const int tid = threadIdx.x;

    s_d[tid] = ds[b * TIN + tid];
    __syncthreads();

    // Serial inclusive scan by thread 0 (unambiguously correct).
    if (tid == 0) {
        int acc = 0;
        for (int i = 0; i < TIN; i++) {
            acc += s_d[i];
            s_cum[i] = acc;
        }
    }
    __syncthreads();

    // Init map to -1 (zero-fill marker), coalesced.
#pragma unroll
    for (int k = 0; k < TOUT / THREADS; k++)
        g_map[b * TOUT + k * THREADS + tid] = -1;
    __syncthreads();

    // Scatter: thread t owns input row t, writes its [left, cum) frames.
    const int cum  = s_cum[tid];
    const int left = cum - s_d[tid];
    for (int f = left; f < cum; f++)
        g_map[b * TOUT + f] = tid;
}

__global__ __launch_bounds__(THREADS)
void lr_gather(const float4* __restrict__ xs,
               float4* __restrict__ out)
{
    const int b      = blockIdx.x;
    const int frame0 = blockIdx.y * FPB;
    const int tid    = threadIdx.x;

    const float4* __restrict__ xsb  = xs  + (size_t)b * TIN  * DIM4;
    float4* __restrict__       outb = out + (size_t)b * TOUT * DIM4;

#pragma unroll
    for (int it = 0; it < ITERS; it++) {
        const int item = it * THREADS + tid;
        const int f    = frame0 + item / DIM4;
        const int slot = item % DIM4;

        const int row = g_map[b * TOUT + f];
        float4 val = make_float4(0.f, 0.f, 0.f, 0.f);
        if (row >= 0)
            val = xsb[row * DIM4 + slot];
        outb[f * DIM4 + slot] = val;
    }
}

extern "C" void kernel_launch(void* const* d_in, const int* in_sizes, int n_in,
                              void* d_out, int out_size)
{
    const float* xs = (const float*)d_in[0];
    const int*   ds = (const int*)d_in[1];
    float*       out = (float*)d_out;

    lr_build_map<<<BATCH, THREADS>>>(ds);

    dim3 grid(BATCH, TOUT / FPB);   // 8 x 256 = 2048 blocks
    lr_gather<<<grid, THREADS>>>((const float4*)xs, (float4*)out);
}

// round 4
// speedup vs baseline: 1.2424x; 1.2424x over previous
#include <cuda_runtime.h>

// LengthRegulator: ys[b, f, :] = xs[b, i, :] where cum[b,i-1] <= f < cum[b,i],
// else 0.  cum = inclusive cumsum of ds along axis 1.
//
//   A: per batch, shuffle-scan ds -> scatter frame->row map (-1 = zero).
//   B: gather rows via the map (pure bandwidth, 6-deep MLP).

#define BATCH   8
#define TIN     512
#define TOUT    4096
#define DIM     384
#define DIM4    (DIM / 4)          // 96 float4 per row
#define FPB     32                 // frames per block in gather
#define THREADS 512
#define ITERS   ((FPB * DIM4) / THREADS)  // 6

__device__ int g_map[BATCH * TOUT];

__global__ __launch_bounds__(THREADS)
void lr_build_map(const int* __restrict__ ds)
{
    __shared__ int s_wsum[16];

    const int b    = blockIdx.x;
    const int tid  = threadIdx.x;
    const int lane = tid & 31;
    const int wid  = tid >> 5;

    const int d = ds[b * TIN + tid];

    // warp-level inclusive scan
    int v = d;
#pragma unroll
    for (int off = 1; off < 32; off <<= 1) {
        int n = __shfl_up_sync(0xffffffffu, v, off);
        if (lane >= off) v += n;
    }
    if (lane == 31) s_wsum[wid] = v;

    // init map to -1 while scan propagates (coalesced, no dependence)
#pragma unroll
    for (int k = 0; k < TOUT / THREADS; k++)
        g_map[b * TOUT + k * THREADS + tid] = -1;
    __syncthreads();

    // scan the 16 warp totals in warp 0
    if (wid == 0 && lane < 16) {
        int w = s_wsum[lane];
#pragma unroll
        for (int off = 1; off < 16; off <<= 1) {
            int n = __shfl_up_sync(0x0000ffffu, w, off);
            if (lane >= off) w += n;
        }
        s_wsum[lane] = w;   // inclusive warp-prefix
    }
    __syncthreads();

    const int cum  = v + (wid > 0 ? s_wsum[wid - 1] : 0);
    const int left = cum - d;

    // scatter: thread t owns input row t, writes its [left, cum) frames
    for (int f = left; f < cum; f++)
        g_map[b * TOUT + f] = tid;
}

__global__ __launch_bounds__(THREADS)
void lr_gather(const float4* __restrict__ xs,
               float4* __restrict__ out)
{
    const int b      = blockIdx.x;
    const int frame0 = blockIdx.y * FPB;
    const int tid    = threadIdx.x;

    const float4* __restrict__ xsb  = xs  + (size_t)b * TIN  * DIM4;
    float4* __restrict__       outb = out + (size_t)b * TOUT * DIM4;

    int   f[ITERS], slot[ITERS], row[ITERS];
    float4 val[ITERS];

    // phase 1: indices (map reads are warp-uniform -> L1 broadcast)
#pragma unroll
    for (int it = 0; it < ITERS; it++) {
        const int item = it * THREADS + tid;
        f[it]    = frame0 + item / DIM4;
        slot[it] = item % DIM4;
        row[it]  = g_map[b * TOUT + f[it]];
    }

    // phase 2: 6 independent loads in flight
#pragma unroll
    for (int it = 0; it < ITERS; it++) {
        val[it] = make_float4(0.f, 0.f, 0.f, 0.f);
        if (row[it] >= 0)
            val[it] = xsb[row[it] * DIM4 + slot[it]];
    }

    // phase 3: stores
#pragma unroll
    for (int it = 0; it < ITERS; it++)
        outb[f[it] * DIM4 + slot[it]] = val[it];
}

extern "C" void kernel_launch(void* const* d_in, const int* in_sizes, int n_in,
                              void* d_out, int out_size)
{
    const float* xs = (const float*)d_in[0];
    const int*   ds = (const int*)d_in[1];
    float*       out = (float*)d_out;

    lr_build_map<<<BATCH, THREADS>>>(ds);

    dim3 grid(BATCH, TOUT / FPB);   // 8 x 128 = 1024 blocks
    lr_gather<<<grid, THREADS>>>((const float4*)xs, (float4*)out);
}

// round 5
// speedup vs baseline: 1.5065x; 1.2126x over previous
#include <cuda_runtime.h>

// LengthRegulator, fully fused:
// ys[b, f, :] = xs[b, i, :] where cum[b,i-1] <= f < cum[b,i], else 0.
//
// One kernel. Each block: shuffle-scan ds[b,:] (2 KB, L1/L2-hit), scatter its
// own 16-frame window's frame->row map into shared (-1 = zero), then copy.

#define BATCH   8
#define TIN     512
#define TOUT    4096
#define DIM4    96                 // 384/4 float4 per row
#define FPB     16                 // frames per block
#define THREADS 512
#define ITERS   ((FPB * DIM4) / THREADS)  // 3

__global__ __launch_bounds__(THREADS)
void lr_fused(const float4* __restrict__ xs,
              const int* __restrict__ ds,
              float4* __restrict__ out)
{
    __shared__ int s_wsum[16];
    __shared__ int s_map[FPB];

    const int b      = blockIdx.x;
    const int frame0 = blockIdx.y * FPB;
    const int tid    = threadIdx.x;
    const int lane   = tid & 31;
    const int wid    = tid >> 5;

    const int d = ds[b * TIN + tid];

    // warp-level inclusive scan (validated in R4)
    int v = d;
#pragma unroll
    for (int off = 1; off < 32; off <<= 1) {
        int n = __shfl_up_sync(0xffffffffu, v, off);
        if (lane >= off) v += n;
    }
    if (lane == 31) s_wsum[wid] = v;
    if (tid < FPB)  s_map[tid] = -1;
    __syncthreads();

    if (wid == 0 && lane < 16) {
        int w = s_wsum[lane];
#pragma unroll
        for (int off = 1; off < 16; off <<= 1) {
            int n = __shfl_up_sync(0x0000ffffu, w, off);
            if (lane >= off) w += n;
        }
        s_wsum[lane] = w;           // inclusive warp-prefix
    }
    __syncthreads();

    const int cum  = v + (wid > 0 ? s_wsum[wid - 1] : 0);
    const int left = cum - d;

    // scatter this row's frames intersected with our window (disjoint writes)
    int lo = left < frame0 ? frame0 : left;
    int hi = cum  > frame0 + FPB ? frame0 + FPB : cum;
    for (int f = lo; f < hi; f++)
        s_map[f - frame0] = tid;
    __syncthreads();

    const float4* __restrict__ xsb  = xs  + (size_t)b * TIN  * DIM4;
    float4* __restrict__       outb = out + (size_t)(b * TOUT + frame0) * DIM4;

    // copy: simple loop (R3-proven perf shape), incremental index math
    int fl   = tid / DIM4;          // frame-in-block 0..15
    int slot = tid - fl * DIM4;     // 0..95
#pragma unroll
    for (int it = 0; it < ITERS; it++) {
        const int row = s_map[fl];
        float4 val = make_float4(0.f, 0.f, 0.f, 0.f);
        if (row >= 0)
            val = xsb[row * DIM4 + slot];
        outb[fl * DIM4 + slot] = val;

        // advance by THREADS=512 items: +5 frames, +32 slots (wraps <= once)
        slot += 32; fl += 5;
        if (slot >= DIM4) { slot -= DIM4; fl++; }
    }
}

extern "C" void kernel_launch(void* const* d_in, const int* in_sizes, int n_in,
                              void* d_out, int out_size)
{
    const float* xs = (const float*)d_in[0];
    const int*   ds = (const int*)d_in[1];
    float*       out = (float*)d_out;

    dim3 grid(BATCH, TOUT / FPB);   // 8 x 256 = 2048 blocks
    lr_fused<<<grid, THREADS>>>((const float4*)xs, ds, (float4*)out);
}

// round 6
// speedup vs baseline: 1.8151x; 1.2049x over previous
#include <cuda_runtime.h>

// LengthRegulator, fused single kernel:
// ys[b, f, :] = xs[b, i, :] where cum[b,i-1] <= f < cum[b,i], else 0.
//
// Each block: shuffle-scan ds[b,:] (L2-hit), scatter its 32-frame window's
// frame->row map into shared (-1 = zero), then a 3-phase batched copy with
// 6 independent LDG.128 in flight per thread.

#define BATCH   8
#define TIN     512
#define TOUT    4096
#define DIM4    96                 // 384/4 float4 per row
#define FPB     32                 // frames per block
#define THREADS 512
#define ITERS   ((FPB * DIM4) / THREADS)  // 6

__global__ __launch_bounds__(THREADS, 1)
void lr_fused(const float4* __restrict__ xs,
              const int* __restrict__ ds,
              float4* __restrict__ out)
{
    __shared__ int s_wsum[16];
    __shared__ int s_map[FPB];

    const int b      = blockIdx.x;
    const int frame0 = blockIdx.y * FPB;
    const int tid    = threadIdx.x;
    const int lane   = tid & 31;
    const int wid    = tid >> 5;

    const int d = ds[b * TIN + tid];

    // warp-level inclusive scan (validated R4/R5)
    int v = d;
#pragma unroll
    for (int off = 1; off < 32; off <<= 1) {
        int n = __shfl_up_sync(0xffffffffu, v, off);
        if (lane >= off) v += n;
    }
    if (lane == 31) s_wsum[wid] = v;
    if (tid < FPB)  s_map[tid] = -1;
    __syncthreads();

    if (wid == 0 && lane < 16) {
        int w = s_wsum[lane];
#pragma unroll
        for (int off = 1; off < 16; off <<= 1) {
            int n = __shfl_up_sync(0x0000ffffu, w, off);
            if (lane >= off) w += n;
        }
        s_wsum[lane] = w;           // inclusive warp-prefix
    }
    __syncthreads();

    const int cum  = v + (wid > 0 ? s_wsum[wid - 1] : 0);
    const int left = cum - d;

    // scatter this row's frames intersected with our window (disjoint writes)
    int lo = left < frame0 ? frame0 : left;
    int hi = cum  > frame0 + FPB ? frame0 + FPB : cum;
    for (int f = lo; f < hi; f++)
        s_map[f - frame0] = tid;
    __syncthreads();

    const float4* __restrict__ xsb  = xs  + (size_t)b * TIN  * DIM4;
    float4* __restrict__       outb = out + (size_t)(b * TOUT + frame0) * DIM4;

    // three-phase batched copy; arrays promoted to regs (launch_bounds grants them)
    int fl[ITERS], sl[ITERS], row[ITERS];
#pragma unroll
    for (int it = 0; it < ITERS; it++) {
        const int item = it * THREADS + tid;
        fl[it]  = item / DIM4;
        sl[it]  = item - fl[it] * DIM4;
        row[it] = s_map[fl[it]];
    }

    float4 val[ITERS];
#pragma unroll
    for (int it = 0; it < ITERS; it++) {
        val[it] = make_float4(0.f, 0.f, 0.f, 0.f);
        if (row[it] >= 0)
            val[it] = xsb[row[it] * DIM4 + sl[it]];
    }

#pragma unroll
    for (int it = 0; it < ITERS; it++)
        outb[fl[it] * DIM4 + sl[it]] = val[it];
}

extern "C" void kernel_launch(void* const* d_in, const int* in_sizes, int n_in,
                              void* d_out, int out_size)
{
    const float* xs = (const float*)d_in[0];
    const int*   ds = (const int*)d_in[1];
    float*       out = (float*)d_out;

    dim3 grid(BATCH, TOUT / FPB);   // 8 x 128 = 1024 blocks
    lr_fused<<<grid, THREADS>>>((const float4*)xs, ds, (float4*)out);
}